// round 4
// baseline (speedup 1.0000x reference)
#include <cuda_runtime.h>
#include <cuda_bf16.h>

// Problem constants (fixed by the reference)
#define NNODES 50000
#define NEDGES 800000
#define D      64
#define NCLS   16

// Scratch (device globals, float4-typed for guaranteed 16B alignment; ~13 MB)
__device__ float4 g_t1[NNODES * NCLS / 4];   // M1 x
__device__ float4 g_u2[NNODES * NCLS / 4];   // M2 x
__device__ float4 g_u3[NNODES * NCLS / 4];   // M3 x
__device__ float4 g_t2[NNODES * NCLS / 4];   // w + M2 x
__device__ float  g_deg[NNODES];             // in-degree
__device__ float  g_T[4 * D * D];            // W2r*W1r, W2r*W1o, W2o*W1r, W2o*W1o
__device__ float  g_M[3 * NCLS * D];         // M1, M2, M3
__device__ float  g_v[2 * NCLS];             // v1, c
__device__ int    g_is64;                    // 1 if edge_index is int64, 0 if int32

// ---------------------------------------------------------------------------
// Detect index dtype: int64 indices in [0,50000) have all-zero hi words.
// ---------------------------------------------------------------------------
__global__ void detect_kernel(const unsigned int* __restrict__ widx) {
    // single block, 256 threads; check hi words of first 4096 8-byte slots
    __shared__ int any_nonzero;
    if (threadIdx.x == 0) any_nonzero = 0;
    __syncthreads();
    unsigned int acc = 0;
    for (int i = threadIdx.x; i < 4096; i += 256) acc |= widx[2 * i + 1];
    if (acc) any_nonzero = 1;
    __syncthreads();
    if (threadIdx.x == 0) g_is64 = any_nonzero ? 0 : 1;
}

// ---------------------------------------------------------------------------
// Stage A: four 64x64 weight products into g_T
// ---------------------------------------------------------------------------
__global__ __launch_bounds__(256) void wcombA_kernel(
        const float* __restrict__ W1r, const float* __restrict__ W1o,
        const float* __restrict__ W2r, const float* __restrict__ W2o) {
    const float* L = (blockIdx.x < 2) ? W2r : W2o;
    const float* R = (blockIdx.x & 1) ? W1o : W1r;
    float* T = g_T + blockIdx.x * (D * D);
    for (int idx = threadIdx.x; idx < D * D; idx += 256) {
        const int o = idx >> 6, k = idx & 63;
        float s = 0.f;
        for (int m = 0; m < D; m++) s += L[o * D + m] * R[m * D + k];
        T[idx] = s;
    }
}

// ---------------------------------------------------------------------------
// Stage B: fold W_lin in, plus bias vectors
//   M1 = Wl*T0, M2 = Wl*(T1+T2), M3 = Wl*T3
//   v1 = Wl*(W2r b1),  c = Wl*(W2o b1 + b2) + bl
// ---------------------------------------------------------------------------
__global__ __launch_bounds__(256) void wcombB_kernel(
        const float* __restrict__ Wl, const float* __restrict__ b1,
        const float* __restrict__ b2, const float* __restrict__ bl,
        const float* __restrict__ W2r, const float* __restrict__ W2o) {
    __shared__ float ur[D], uo[D];
    const int t = threadIdx.x;
    if (t < D) {
        float s = 0.f;
        for (int k = 0; k < D; k++) s += W2r[t * D + k] * b1[k];
        ur[t] = s;
    } else if (t < 2 * D) {
        const int m = t - D;
        float s = 0.f;
        for (int k = 0; k < D; k++) s += W2o[m * D + k] * b1[k];
        uo[m] = s;
    }
    __syncthreads();

    for (int idx = t; idx < 3 * NCLS * D; idx += 256) {
        const int which = idx / (NCLS * D);
        const int rem = idx - which * (NCLS * D);
        const int r = rem >> 6, k = rem & 63;
        float s = 0.f;
        if (which == 0) {
            for (int m = 0; m < D; m++)
                s += Wl[r * D + m] * g_T[m * D + k];
        } else if (which == 1) {
            for (int m = 0; m < D; m++)
                s += Wl[r * D + m] * (g_T[D * D + m * D + k] + g_T[2 * D * D + m * D + k]);
        } else {
            for (int m = 0; m < D; m++)
                s += Wl[r * D + m] * g_T[3 * D * D + m * D + k];
        }
        g_M[idx] = s;
    }

    if (t < NCLS) {
        float s = 0.f;
        for (int m = 0; m < D; m++) s += Wl[t * D + m] * ur[m];
        g_v[t] = s;
    } else if (t < 2 * NCLS) {
        const int r = t - NCLS;
        float s = 0.f;
        for (int m = 0; m < D; m++) s += Wl[r * D + m] * (uo[m] + b2[m]);
        g_v[NCLS + r] = s + bl[r];
    }
}

// ---------------------------------------------------------------------------
// Project x to 16-dim: t1 = M1 x, u2 = M2 x, u3 = M3 x.
// Also zeroes d_out (used as w accumulator) and g_deg.
// 16 nodes per 256-thread block; lane = class.
// ---------------------------------------------------------------------------
__global__ __launch_bounds__(256) void transform_kernel(
        const float* __restrict__ x, float* __restrict__ w_out) {
    __shared__ float sM[3 * NCLS * D];   // 12 KB
    __shared__ float sx[16 * D];         // 4 KB
    const int tid = threadIdx.x;
    for (int i = tid; i < 3 * NCLS * D; i += 256) sM[i] = g_M[i];
    const int nodeBase = blockIdx.x * 16;
    // 256 threads load 16 nodes x 64 floats = 256 float4
    ((float4*)sx)[tid] = ((const float4*)(x + (size_t)nodeBase * D))[tid];
    __syncthreads();

    const int j = tid >> 4;    // node within block
    const int r = tid & 15;    // class
    const float* xr = &sx[j * D];
    const float* m1 = &sM[r * D];
    const float* m2 = &sM[NCLS * D + r * D];
    const float* m3 = &sM[2 * NCLS * D + r * D];
    float a1 = 0.f, a2 = 0.f, a3 = 0.f;
    for (int k = 0; k < D; k++) {
        const float xv = xr[k];
        a1 += m1[k] * xv;
        a2 += m2[k] * xv;
        a3 += m3[k] * xv;
    }
    const int i = nodeBase + j;
    ((float*)g_t1)[i * NCLS + r] = a1;
    ((float*)g_u2)[i * NCLS + r] = a2;
    ((float*)g_u3)[i * NCLS + r] = a3;
    w_out[i * NCLS + r] = 0.f;
    if (r == 0) g_deg[i] = 0.f;
}

// ---------------------------------------------------------------------------
// 16-wide scatter: dst[e] += src[e] features (4x float4 RED per edge).
// Handles int32 or int64 edge indices via g_is64 (uniform branch).
// PASS 0: src = g_t1, accumulate degree.  PASS 1: src = g_t2.
// ---------------------------------------------------------------------------
template <int PASS>
__global__ __launch_bounds__(256) void scatter16_kernel(
        float* __restrict__ dst_feat, const void* __restrict__ eidx) {
    const int e = blockIdx.x * 256 + threadIdx.x;     // grid exact: 3125*256 = 800000
    int s, d;
    if (g_is64) {
        const long long* ei = (const long long*)eidx;
        s = (int)ei[e];
        d = (int)ei[NEDGES + e];
    } else {
        const int* ei = (const int*)eidx;
        s = ei[e];
        d = ei[NEDGES + e];
    }
    const float4* v = (PASS == 0) ? &g_t1[s * (NCLS / 4)] : &g_t2[s * (NCLS / 4)];
    float4* o = (float4*)(dst_feat + d * NCLS);
    const float4 v0 = v[0], v1 = v[1], v2 = v[2], v3 = v[3];
    atomicAdd(o + 0, v0);
    atomicAdd(o + 1, v1);
    atomicAdd(o + 2, v2);
    atomicAdd(o + 3, v3);
    if (PASS == 0) atomicAdd(&g_deg[d], 1.0f);
}

// ---------------------------------------------------------------------------
// t2 = w + u2 ;  out = u3 + deg*v1 + c   (w lives in d_out, overwritten here)
// One float4 (4 classes) per thread.
// ---------------------------------------------------------------------------
__global__ __launch_bounds__(256) void combine_kernel(float* __restrict__ d_out) {
    const int q = blockIdx.x * 256 + threadIdx.x;     // < 200000 float4 slots
    const int i = q >> 2;                             // node
    const int rb = (q & 3) * 4;                       // class base
    float4 w = ((float4*)d_out)[q];
    const float4 u2 = g_u2[q];
    g_t2[q] = make_float4(w.x + u2.x, w.y + u2.y, w.z + u2.z, w.w + u2.w);
    const float dg = g_deg[i];
    const float4 u3 = g_u3[q];
    float4 r;
    r.x = u3.x + dg * g_v[rb + 0] + g_v[NCLS + rb + 0];
    r.y = u3.y + dg * g_v[rb + 1] + g_v[NCLS + rb + 1];
    r.z = u3.z + dg * g_v[rb + 2] + g_v[NCLS + rb + 2];
    r.w = u3.w + dg * g_v[rb + 3] + g_v[NCLS + rb + 3];
    ((float4*)d_out)[q] = r;
}

// ---------------------------------------------------------------------------
extern "C" void kernel_launch(void* const* d_in, const int* in_sizes, int n_in,
                              void* d_out, int out_size) {
    const float* x   = (const float*)d_in[0];
    const void*  eix = d_in[1];
    const float* W1r = (const float*)d_in[2];
    const float* b1  = (const float*)d_in[3];
    const float* W1o = (const float*)d_in[4];
    const float* W2r = (const float*)d_in[5];
    const float* b2  = (const float*)d_in[6];
    const float* W2o = (const float*)d_in[7];
    const float* Wl  = (const float*)d_in[8];
    const float* bl  = (const float*)d_in[9];
    float* out = (float*)d_out;

    // Detect int32 vs int64 edge indices (deterministic, data-driven)
    detect_kernel<<<1, 256>>>((const unsigned int*)eix);

    // Weight folding (tiny)
    wcombA_kernel<<<4, 256>>>(W1r, W1o, W2r, W2o);
    wcombB_kernel<<<1, 256>>>(Wl, b1, b2, bl, W2r, W2o);

    // Project to 16-dim; zero w (=d_out) and deg
    transform_kernel<<<3125, 256>>>(x, out);

    // w = A t1 (and deg)
    scatter16_kernel<0><<<3125, 256>>>(out, eix);

    // t2 = w + u2 ; out = u3 + deg*v1 + c   (200000 float4 slots / 256)
    combine_kernel<<<782, 256>>>(out);

    // out += A t2
    scatter16_kernel<1><<<3125, 256>>>(out, eix);
}

// round 5
// speedup vs baseline: 1.7980x; 1.7980x over previous
#include <cuda_runtime.h>
#include <cuda_bf16.h>

// Problem constants (fixed by the reference)
#define NNODES 50000
#define NEDGES 800000
#define D      64
#define NCLS   16

// Scratch (device globals, float4-typed where 16B alignment is required)
__device__ float4 g_t1[NNODES * NCLS / 4];   // M1 x
__device__ float4 g_u2[NNODES * NCLS / 4];   // M2 x
__device__ float4 g_u3[NNODES * NCLS / 4];   // M3 x
__device__ float4 g_t2[NNODES * NCLS / 4];   // w + M2 x
__device__ float  g_deg[NNODES];             // in-degree
__device__ float  g_T[4 * D * D];            // W2r*W1r, W2r*W1o, W2o*W1r, W2o*W1o
__device__ float  g_M[3 * NCLS * D];         // M1, M2, M3
__device__ float  g_v[2 * NCLS];             // v1, c
__device__ int    g_is64;                    // 1 if edge_index is int64
__device__ int2   g_edge[NEDGES];            // packed (src, dst) int32

// ---------------------------------------------------------------------------
// Detect index dtype: int64 indices in [0,50000) have all-zero hi words.
// ---------------------------------------------------------------------------
__global__ void detect_kernel(const unsigned int* __restrict__ widx) {
    __shared__ int any_nonzero;
    if (threadIdx.x == 0) any_nonzero = 0;
    __syncthreads();
    unsigned int acc = 0;
    for (int i = threadIdx.x; i < 4096; i += 256) acc |= widx[2 * i + 1];
    if (acc) any_nonzero = 1;
    __syncthreads();
    if (threadIdx.x == 0) g_is64 = any_nonzero ? 0 : 1;
}

// ---------------------------------------------------------------------------
// Pack edge indices into int2 (branch once per thread, uniform).
// ---------------------------------------------------------------------------
__global__ __launch_bounds__(256) void edge_prep_kernel(const void* __restrict__ eidx) {
    const int e = blockIdx.x * 256 + threadIdx.x;      // grid exact: 3125*256
    int s, d;
    if (g_is64) {
        const long long* ei = (const long long*)eidx;
        s = (int)ei[e];
        d = (int)ei[NEDGES + e];
    } else {
        const int* ei = (const int*)eidx;
        s = ei[e];
        d = ei[NEDGES + e];
    }
    g_edge[e] = make_int2(s, d);
}

// ---------------------------------------------------------------------------
// Stage A: four 64x64 weight products into g_T
// ---------------------------------------------------------------------------
__global__ __launch_bounds__(256) void wcombA_kernel(
        const float* __restrict__ W1r, const float* __restrict__ W1o,
        const float* __restrict__ W2r, const float* __restrict__ W2o) {
    const float* L = (blockIdx.x < 2) ? W2r : W2o;
    const float* R = (blockIdx.x & 1) ? W1o : W1r;
    float* T = g_T + blockIdx.x * (D * D);
    for (int idx = threadIdx.x; idx < D * D; idx += 256) {
        const int o = idx >> 6, k = idx & 63;
        float s = 0.f;
        for (int m = 0; m < D; m++) s += L[o * D + m] * R[m * D + k];
        T[idx] = s;
    }
}

// ---------------------------------------------------------------------------
// Stage B: fold W_lin in, plus bias vectors
// ---------------------------------------------------------------------------
__global__ __launch_bounds__(256) void wcombB_kernel(
        const float* __restrict__ Wl, const float* __restrict__ b1,
        const float* __restrict__ b2, const float* __restrict__ bl,
        const float* __restrict__ W2r, const float* __restrict__ W2o) {
    __shared__ float ur[D], uo[D];
    const int t = threadIdx.x;
    if (t < D) {
        float s = 0.f;
        for (int k = 0; k < D; k++) s += W2r[t * D + k] * b1[k];
        ur[t] = s;
    } else if (t < 2 * D) {
        const int m = t - D;
        float s = 0.f;
        for (int k = 0; k < D; k++) s += W2o[m * D + k] * b1[k];
        uo[m] = s;
    }
    __syncthreads();

    for (int idx = t; idx < 3 * NCLS * D; idx += 256) {
        const int which = idx / (NCLS * D);
        const int rem = idx - which * (NCLS * D);
        const int r = rem >> 6, k = rem & 63;
        float s = 0.f;
        if (which == 0) {
            for (int m = 0; m < D; m++)
                s += Wl[r * D + m] * g_T[m * D + k];
        } else if (which == 1) {
            for (int m = 0; m < D; m++)
                s += Wl[r * D + m] * (g_T[D * D + m * D + k] + g_T[2 * D * D + m * D + k]);
        } else {
            for (int m = 0; m < D; m++)
                s += Wl[r * D + m] * g_T[3 * D * D + m * D + k];
        }
        g_M[idx] = s;
    }

    if (t < NCLS) {
        float s = 0.f;
        for (int m = 0; m < D; m++) s += Wl[t * D + m] * ur[m];
        g_v[t] = s;
    } else if (t < 2 * NCLS) {
        const int r = t - NCLS;
        float s = 0.f;
        for (int m = 0; m < D; m++) s += Wl[r * D + m] * (uo[m] + b2[m]);
        g_v[NCLS + r] = s + bl[r];
    }
}

// ---------------------------------------------------------------------------
// Project x to 16-dim: t1 = M1 x, u2 = M2 x, u3 = M3 x.
// Padded shared (stride 65) -> conflict-free: bank = (row + col) mod 32.
// 16 nodes per 256-thread block; lane = class.
// ---------------------------------------------------------------------------
#define SMP 65   // padded row stride for shared M and x

__global__ __launch_bounds__(256) void transform_kernel(
        const float* __restrict__ x, float* __restrict__ w_out) {
    __shared__ float sM[3 * NCLS * SMP];   // 48 rows x 65
    __shared__ float sx[16 * SMP];         // 16 rows x 65
    const int tid = threadIdx.x;
    // Load M with padding (48*64 = 3072 elements)
    for (int i = tid; i < 3 * NCLS * D; i += 256) {
        const int row = i >> 6, col = i & 63;
        sM[row * SMP + col] = g_M[i];
    }
    // Load x tile: 256 threads x 1 float4 = 16 nodes x 64 floats
    const int nodeBase = blockIdx.x * 16;
    {
        const float4 v = ((const float4*)(x + (size_t)nodeBase * D))[tid];
        const int el = tid * 4;             // linear element in tile
        const int row = el >> 6, col = el & 63;
        float* p = &sx[row * SMP + col];
        p[0] = v.x; p[1] = v.y; p[2] = v.z; p[3] = v.w;
    }
    __syncthreads();

    const int j = tid >> 4;    // node within block
    const int r = tid & 15;    // class
    const float* xr = &sx[j * SMP];
    const float* m1 = &sM[r * SMP];
    const float* m2 = &sM[(NCLS + r) * SMP];
    const float* m3 = &sM[(2 * NCLS + r) * SMP];
    float a1 = 0.f, a2 = 0.f, a3 = 0.f;
    for (int k = 0; k < D; k++) {
        const float xv = xr[k];
        a1 += m1[k] * xv;
        a2 += m2[k] * xv;
        a3 += m3[k] * xv;
    }
    const int i = nodeBase + j;
    ((float*)g_t1)[i * NCLS + r] = a1;
    ((float*)g_u2)[i * NCLS + r] = a2;
    ((float*)g_u3)[i * NCLS + r] = a3;
    w_out[i * NCLS + r] = 0.f;
    if (r == 0) g_deg[i] = 0.f;
}

// ---------------------------------------------------------------------------
// 16-wide scatter: dst[e] += src[e] features (4x float4 RED per edge).
// PASS 0: src = g_t1, accumulate degree.  PASS 1: src = g_t2.
// ---------------------------------------------------------------------------
template <int PASS>
__global__ __launch_bounds__(256) void scatter16_kernel(float* __restrict__ dst_feat) {
    const int e = blockIdx.x * 256 + threadIdx.x;     // grid exact: 3125*256 = 800000
    const int2 sd = g_edge[e];
    const float4* v = (PASS == 0) ? &g_t1[sd.x * (NCLS / 4)] : &g_t2[sd.x * (NCLS / 4)];
    float4* o = (float4*)(dst_feat + sd.y * NCLS);
    const float4 v0 = v[0], v1 = v[1], v2 = v[2], v3 = v[3];
    atomicAdd(o + 0, v0);
    atomicAdd(o + 1, v1);
    atomicAdd(o + 2, v2);
    atomicAdd(o + 3, v3);
    if (PASS == 0) atomicAdd(&g_deg[sd.y], 1.0f);
}

// ---------------------------------------------------------------------------
// t2 = w + u2 ;  out = u3 + deg*v1 + c   (w lives in d_out, overwritten here)
// ---------------------------------------------------------------------------
__global__ __launch_bounds__(256) void combine_kernel(float* __restrict__ d_out) {
    const int q = blockIdx.x * 256 + threadIdx.x;     // < 200000 float4 slots
    const int i = q >> 2;                             // node
    const int rb = (q & 3) * 4;                       // class base
    float4 w = ((float4*)d_out)[q];
    const float4 u2 = g_u2[q];
    g_t2[q] = make_float4(w.x + u2.x, w.y + u2.y, w.z + u2.z, w.w + u2.w);
    const float dg = g_deg[i];
    const float4 u3 = g_u3[q];
    float4 r;
    r.x = u3.x + dg * g_v[rb + 0] + g_v[NCLS + rb + 0];
    r.y = u3.y + dg * g_v[rb + 1] + g_v[NCLS + rb + 1];
    r.z = u3.z + dg * g_v[rb + 2] + g_v[NCLS + rb + 2];
    r.w = u3.w + dg * g_v[rb + 3] + g_v[NCLS + rb + 3];
    ((float4*)d_out)[q] = r;
}

// ---------------------------------------------------------------------------
extern "C" void kernel_launch(void* const* d_in, const int* in_sizes, int n_in,
                              void* d_out, int out_size) {
    const float* x   = (const float*)d_in[0];
    const void*  eix = d_in[1];
    const float* W1r = (const float*)d_in[2];
    const float* b1  = (const float*)d_in[3];
    const float* W1o = (const float*)d_in[4];
    const float* W2r = (const float*)d_in[5];
    const float* b2  = (const float*)d_in[6];
    const float* W2o = (const float*)d_in[7];
    const float* Wl  = (const float*)d_in[8];
    const float* bl  = (const float*)d_in[9];
    float* out = (float*)d_out;

    // Detect dtype, pack edges to int2
    detect_kernel<<<1, 256>>>((const unsigned int*)eix);
    edge_prep_kernel<<<3125, 256>>>(eix);

    // Weight folding (tiny)
    wcombA_kernel<<<4, 256>>>(W1r, W1o, W2r, W2o);
    wcombB_kernel<<<1, 256>>>(Wl, b1, b2, bl, W2r, W2o);

    // Project to 16-dim; zero w (=d_out) and deg
    transform_kernel<<<3125, 256>>>(x, out);

    // w = A t1 (and deg)
    scatter16_kernel<0><<<3125, 256>>>(out);

    // t2 = w + u2 ; out = u3 + deg*v1 + c
    combine_kernel<<<782, 256>>>(out);

    // out += A t2
    scatter16_kernel<1><<<3125, 256>>>(out);
}

// round 6
// speedup vs baseline: 2.2975x; 1.2778x over previous
#include <cuda_runtime.h>
#include <cuda_bf16.h>

// Problem constants (fixed by the reference)
#define NNODES 50000
#define NEDGES 800000
#define D      64
#define NCLS   16

// Scratch (device globals, float4-typed where 16B alignment is required)
__device__ float4 g_t1[NNODES * NCLS / 4];   // M1 x
__device__ float4 g_u2[NNODES * NCLS / 4];   // M2 x
__device__ float4 g_u3[NNODES * NCLS / 4];   // M3 x
__device__ float4 g_t2[NNODES * NCLS / 4];   // w + M2 x
__device__ float  g_deg[NNODES];             // in-degree
__device__ float  g_M[3 * NCLS * D];         // M1, M2, M3
__device__ float  g_v[2 * NCLS];             // v1, c
__device__ int    g_is64;                    // 1 if edge_index is int64
__device__ int2   g_edge[NEDGES];            // packed (src, dst) int32

// ---------------------------------------------------------------------------
// Detect index dtype: int64 indices in [0,50000) have all-zero hi words.
// ---------------------------------------------------------------------------
__global__ void detect_kernel(const unsigned int* __restrict__ widx) {
    __shared__ int any_nonzero;
    if (threadIdx.x == 0) any_nonzero = 0;
    __syncthreads();
    unsigned int acc = 0;
    for (int i = threadIdx.x; i < 4096; i += 256) acc |= widx[2 * i + 1];
    if (acc) any_nonzero = 1;
    __syncthreads();
    if (threadIdx.x == 0) g_is64 = any_nonzero ? 0 : 1;
}

// ---------------------------------------------------------------------------
// Pack edge indices into int2 (branch once per thread, uniform).
// ---------------------------------------------------------------------------
__global__ __launch_bounds__(256) void edge_prep_kernel(const void* __restrict__ eidx) {
    const int e = blockIdx.x * 256 + threadIdx.x;      // grid exact: 3125*256
    int s, d;
    if (g_is64) {
        const long long* ei = (const long long*)eidx;
        s = (int)ei[e];
        d = (int)ei[NEDGES + e];
    } else {
        const int* ei = (const int*)eidx;
        s = ei[e];
        d = ei[NEDGES + e];
    }
    g_edge[e] = make_int2(s, d);
}

// ---------------------------------------------------------------------------
// Unified weight fold, one block, all operands staged in shared memory.
//   Phase 1: P_r = Wl*W2r, P_o = Wl*W2o; v1 = Wl*(W2r b1); c = Wl*(W2o b1+b2)+bl
//   Phase 2 (reuse buffers with W1r/W1o):
//     M1 = P_r*W1r, M2 = P_r*W1o + P_o*W1r, M3 = P_o*W1o
// Shared: 2x16KB (W pair) + 4KB (Wl) + 2x4KB (P) + vectors ~= 44.7KB
// ---------------------------------------------------------------------------
__global__ __launch_bounds__(256) void wfold_kernel(
        const float* __restrict__ W1r, const float* __restrict__ b1,
        const float* __restrict__ W1o, const float* __restrict__ W2r,
        const float* __restrict__ b2,  const float* __restrict__ W2o,
        const float* __restrict__ Wl,  const float* __restrict__ bl) {
    __shared__ float sWa[D * D];        // 16KB : W2r then W1r
    __shared__ float sWb[D * D];        // 16KB : W2o then W1o
    __shared__ float sWl[NCLS * D];     // 4KB
    __shared__ float sPr[NCLS * D];     // 4KB
    __shared__ float sPo[NCLS * D];     // 4KB
    __shared__ float sb1[D], sb2[D], sur[D], suo[D];
    const int tid = threadIdx.x;

    // ---- Phase 1 loads: Wl, W2r, W2o, b1, b2 (float4, coalesced) ----
    {
        const int nf4 = D * D / 4;                     // 1024 float4 per 64x64
        for (int i = tid; i < nf4; i += 256) {
            ((float4*)sWa)[i] = ((const float4*)W2r)[i];
            ((float4*)sWb)[i] = ((const float4*)W2o)[i];
        }
        for (int i = tid; i < NCLS * D / 4; i += 256)
            ((float4*)sWl)[i] = ((const float4*)Wl)[i];
        if (tid < D / 4) {
            ((float4*)sb1)[tid] = ((const float4*)b1)[tid];
            ((float4*)sb2)[tid] = ((const float4*)b2)[tid];
        }
    }
    __syncthreads();

    // ur[m] = sum_k W2r[m][k] b1[k]; uo[m] = sum_k W2o[m][k] b1[k]
    if (tid < D) {
        float s = 0.f;
        for (int k = 0; k < D; k++) s += sWa[tid * D + k] * sb1[k];
        sur[tid] = s;
    } else if (tid < 2 * D) {
        const int m = tid - D;
        float s = 0.f;
        for (int k = 0; k < D; k++) s += sWb[m * D + k] * sb1[k];
        suo[m] = s;
    }

    // P_r, P_o : 2048 outputs, 8 per thread. Lanes vary m (contiguous).
    for (int idx = tid; idx < NCLS * D; idx += 256) {
        const int r = idx >> 6, m = idx & 63;
        float pr = 0.f, po = 0.f;
        for (int j = 0; j < D; j++) {
            const float w = sWl[r * D + j];
            pr += w * sWa[j * D + m];
            po += w * sWb[j * D + m];
        }
        sPr[idx] = pr;
        sPo[idx] = po;
    }
    __syncthreads();

    // v1[r], c[r]
    if (tid < NCLS) {
        float s = 0.f;
        for (int m = 0; m < D; m++) s += sWl[tid * D + m] * sur[m];
        g_v[tid] = s;
    } else if (tid < 2 * NCLS) {
        const int r = tid - NCLS;
        float s = 0.f;
        for (int m = 0; m < D; m++) s += sWl[r * D + m] * (suo[m] + sb2[m]);
        g_v[NCLS + r] = s + bl[r];
    }

    // ---- Phase 2 loads: W1r -> sWa, W1o -> sWb ----
    {
        const int nf4 = D * D / 4;
        for (int i = tid; i < nf4; i += 256) {
            ((float4*)sWa)[i] = ((const float4*)W1r)[i];
            ((float4*)sWb)[i] = ((const float4*)W1o)[i];
        }
    }
    __syncthreads();

    // M1/M2/M3 : 3072 outputs, 12 per thread. Lanes vary k (contiguous).
    for (int idx = tid; idx < 3 * NCLS * D; idx += 256) {
        const int which = idx / (NCLS * D);
        const int rem = idx - which * (NCLS * D);
        const int r = rem >> 6, k = rem & 63;
        float s = 0.f;
        if (which == 0) {
            for (int m = 0; m < D; m++) s += sPr[r * D + m] * sWa[m * D + k];
        } else if (which == 1) {
            for (int m = 0; m < D; m++)
                s += sPr[r * D + m] * sWb[m * D + k] + sPo[r * D + m] * sWa[m * D + k];
        } else {
            for (int m = 0; m < D; m++) s += sPo[r * D + m] * sWb[m * D + k];
        }
        g_M[idx] = s;
    }
}

// ---------------------------------------------------------------------------
// Project x to 16-dim: t1 = M1 x, u2 = M2 x, u3 = M3 x.
// Padded shared (stride 65) -> conflict-free: bank = (row + col) mod 32.
// 16 nodes per 256-thread block; lane = class.
// ---------------------------------------------------------------------------
#define SMP 65   // padded row stride for shared M and x

__global__ __launch_bounds__(256) void transform_kernel(
        const float* __restrict__ x, float* __restrict__ w_out) {
    __shared__ float sM[3 * NCLS * SMP];   // 48 rows x 65
    __shared__ float sx[16 * SMP];         // 16 rows x 65
    const int tid = threadIdx.x;
    for (int i = tid; i < 3 * NCLS * D; i += 256) {
        const int row = i >> 6, col = i & 63;
        sM[row * SMP + col] = g_M[i];
    }
    const int nodeBase = blockIdx.x * 16;
    {
        const float4 v = ((const float4*)(x + (size_t)nodeBase * D))[tid];
        const int el = tid * 4;
        const int row = el >> 6, col = el & 63;
        float* p = &sx[row * SMP + col];
        p[0] = v.x; p[1] = v.y; p[2] = v.z; p[3] = v.w;
    }
    __syncthreads();

    const int j = tid >> 4;    // node within block
    const int r = tid & 15;    // class
    const float* xr = &sx[j * SMP];
    const float* m1 = &sM[r * SMP];
    const float* m2 = &sM[(NCLS + r) * SMP];
    const float* m3 = &sM[(2 * NCLS + r) * SMP];
    float a1 = 0.f, a2 = 0.f, a3 = 0.f;
    for (int k = 0; k < D; k++) {
        const float xv = xr[k];
        a1 += m1[k] * xv;
        a2 += m2[k] * xv;
        a3 += m3[k] * xv;
    }
    const int i = nodeBase + j;
    ((float*)g_t1)[i * NCLS + r] = a1;
    ((float*)g_u2)[i * NCLS + r] = a2;
    ((float*)g_u3)[i * NCLS + r] = a3;
    w_out[i * NCLS + r] = 0.f;
    if (r == 0) g_deg[i] = 0.f;
}

// ---------------------------------------------------------------------------
// 16-wide scatter: dst[e] += src[e] features (4x float4 RED per edge).
// PASS 0: src = g_t1, accumulate degree.  PASS 1: src = g_t2.
// ---------------------------------------------------------------------------
template <int PASS>
__global__ __launch_bounds__(256) void scatter16_kernel(float* __restrict__ dst_feat) {
    const int e = blockIdx.x * 256 + threadIdx.x;     // grid exact: 3125*256 = 800000
    const int2 sd = g_edge[e];
    const float4* v = (PASS == 0) ? &g_t1[sd.x * (NCLS / 4)] : &g_t2[sd.x * (NCLS / 4)];
    float4* o = (float4*)(dst_feat + sd.y * NCLS);
    const float4 v0 = v[0], v1 = v[1], v2 = v[2], v3 = v[3];
    atomicAdd(o + 0, v0);
    atomicAdd(o + 1, v1);
    atomicAdd(o + 2, v2);
    atomicAdd(o + 3, v3);
    if (PASS == 0) atomicAdd(&g_deg[sd.y], 1.0f);
}

// ---------------------------------------------------------------------------
// t2 = w + u2 ;  out = u3 + deg*v1 + c   (w lives in d_out, overwritten here)
// ---------------------------------------------------------------------------
__global__ __launch_bounds__(256) void combine_kernel(float* __restrict__ d_out) {
    const int q = blockIdx.x * 256 + threadIdx.x;     // < 200000 float4 slots
    const int i = q >> 2;                             // node
    const int rb = (q & 3) * 4;                       // class base
    float4 w = ((float4*)d_out)[q];
    const float4 u2 = g_u2[q];
    g_t2[q] = make_float4(w.x + u2.x, w.y + u2.y, w.z + u2.z, w.w + u2.w);
    const float dg = g_deg[i];
    const float4 u3 = g_u3[q];
    float4 r;
    r.x = u3.x + dg * g_v[rb + 0] + g_v[NCLS + rb + 0];
    r.y = u3.y + dg * g_v[rb + 1] + g_v[NCLS + rb + 1];
    r.z = u3.z + dg * g_v[rb + 2] + g_v[NCLS + rb + 2];
    r.w = u3.w + dg * g_v[rb + 3] + g_v[NCLS + rb + 3];
    ((float4*)d_out)[q] = r;
}

// ---------------------------------------------------------------------------
extern "C" void kernel_launch(void* const* d_in, const int* in_sizes, int n_in,
                              void* d_out, int out_size) {
    const float* x   = (const float*)d_in[0];
    const void*  eix = d_in[1];
    const float* W1r = (const float*)d_in[2];
    const float* b1  = (const float*)d_in[3];
    const float* W1o = (const float*)d_in[4];
    const float* W2r = (const float*)d_in[5];
    const float* b2  = (const float*)d_in[6];
    const float* W2o = (const float*)d_in[7];
    const float* Wl  = (const float*)d_in[8];
    const float* bl  = (const float*)d_in[9];
    float* out = (float*)d_out;

    // Detect dtype, pack edges to int2
    detect_kernel<<<1, 256>>>((const unsigned int*)eix);
    edge_prep_kernel<<<3125, 256>>>(eix);

    // Single fused weight fold (shared-memory resident)
    wfold_kernel<<<1, 256>>>(W1r, b1, W1o, W2r, b2, W2o, Wl, bl);

    // Project to 16-dim; zero w (=d_out) and deg
    transform_kernel<<<3125, 256>>>(x, out);

    // w = A t1 (and deg)
    scatter16_kernel<0><<<3125, 256>>>(out);

    // t2 = w + u2 ; out = u3 + deg*v1 + c
    combine_kernel<<<782, 256>>>(out);

    // out += A t2
    scatter16_kernel<1><<<3125, 256>>>(out);
}

// round 7
// speedup vs baseline: 2.4758x; 1.0776x over previous
#include <cuda_runtime.h>
#include <cuda_bf16.h>

// Problem constants (fixed by the reference)
#define NNODES 50000
#define NEDGES 800000
#define D      64
#define NCLS   16

// Scratch (device globals, float4-typed where 16B alignment is required)
__device__ float4 g_t1[NNODES * NCLS / 4];   // M1 x
__device__ float4 g_u2[NNODES * NCLS / 4];   // M2 x
__device__ float4 g_u3[NNODES * NCLS / 4];   // M3 x
__device__ float4 g_t2[NNODES * NCLS / 4];   // w + M2 x
__device__ float  g_deg[NNODES];             // in-degree
__device__ float4 g_M4[3 * NCLS * D / 4];    // M1, M2, M3 (float4-aligned)
__device__ float  g_v[2 * NCLS];             // v1, c
__device__ int    g_is64;                    // 1 if edge_index is int64
__device__ int2   g_edge[NEDGES];            // packed (src, dst) int32

// ---------------------------------------------------------------------------
// Fused: dtype detect + unified weight fold (one block, smem-resident).
//   detect: int64 indices in [0,50000) have all-zero hi words.
//   Phase 1: P_r = Wl*W2r, P_o = Wl*W2o; v1 = Wl*(W2r b1); c = Wl*(W2o b1+b2)+bl
//   Phase 2: M1 = P_r*W1r, M2 = P_r*W1o + P_o*W1r, M3 = P_o*W1o
// ---------------------------------------------------------------------------
__global__ __launch_bounds__(256) void dwfold_kernel(
        const unsigned int* __restrict__ widx,
        const float* __restrict__ W1r, const float* __restrict__ b1,
        const float* __restrict__ W1o, const float* __restrict__ W2r,
        const float* __restrict__ b2,  const float* __restrict__ W2o,
        const float* __restrict__ Wl,  const float* __restrict__ bl) {
    __shared__ float sWa[D * D];        // W2r then W1r
    __shared__ float sWb[D * D];        // W2o then W1o
    __shared__ float sWl[NCLS * D];
    __shared__ float sPr[NCLS * D];
    __shared__ float sPo[NCLS * D];
    __shared__ float sb1[D], sb2[D], sur[D], suo[D];
    __shared__ int any_nonzero;
    const int tid = threadIdx.x;

    // ---- dtype detect ----
    if (tid == 0) any_nonzero = 0;
    __syncthreads();
    {
        unsigned int acc = 0;
        for (int i = tid; i < 4096; i += 256) acc |= widx[2 * i + 1];
        if (acc) any_nonzero = 1;
    }

    // ---- Phase 1 loads ----
    {
        const int nf4 = D * D / 4;
        for (int i = tid; i < nf4; i += 256) {
            ((float4*)sWa)[i] = ((const float4*)W2r)[i];
            ((float4*)sWb)[i] = ((const float4*)W2o)[i];
        }
        for (int i = tid; i < NCLS * D / 4; i += 256)
            ((float4*)sWl)[i] = ((const float4*)Wl)[i];
        if (tid < D / 4) {
            ((float4*)sb1)[tid] = ((const float4*)b1)[tid];
            ((float4*)sb2)[tid] = ((const float4*)b2)[tid];
        }
    }
    __syncthreads();
    if (tid == 0) g_is64 = any_nonzero ? 0 : 1;

    if (tid < D) {
        float s = 0.f;
        for (int k = 0; k < D; k++) s += sWa[tid * D + k] * sb1[k];
        sur[tid] = s;
    } else if (tid < 2 * D) {
        const int m = tid - D;
        float s = 0.f;
        for (int k = 0; k < D; k++) s += sWb[m * D + k] * sb1[k];
        suo[m] = s;
    }

    for (int idx = tid; idx < NCLS * D; idx += 256) {
        const int r = idx >> 6, m = idx & 63;
        float pr = 0.f, po = 0.f;
        for (int j = 0; j < D; j++) {
            const float w = sWl[r * D + j];
            pr += w * sWa[j * D + m];
            po += w * sWb[j * D + m];
        }
        sPr[idx] = pr;
        sPo[idx] = po;
    }
    __syncthreads();

    if (tid < NCLS) {
        float s = 0.f;
        for (int m = 0; m < D; m++) s += sWl[tid * D + m] * sur[m];
        g_v[tid] = s;
    } else if (tid < 2 * NCLS) {
        const int r = tid - NCLS;
        float s = 0.f;
        for (int m = 0; m < D; m++) s += sWl[r * D + m] * (suo[m] + sb2[m]);
        g_v[NCLS + r] = s + bl[r];
    }

    // ---- Phase 2 loads: W1r -> sWa, W1o -> sWb ----
    {
        const int nf4 = D * D / 4;
        for (int i = tid; i < nf4; i += 256) {
            ((float4*)sWa)[i] = ((const float4*)W1r)[i];
            ((float4*)sWb)[i] = ((const float4*)W1o)[i];
        }
    }
    __syncthreads();

    for (int idx = tid; idx < 3 * NCLS * D; idx += 256) {
        const int which = idx / (NCLS * D);
        const int rem = idx - which * (NCLS * D);
        const int r = rem >> 6, k = rem & 63;
        float s = 0.f;
        if (which == 0) {
            for (int m = 0; m < D; m++) s += sPr[r * D + m] * sWa[m * D + k];
        } else if (which == 1) {
            for (int m = 0; m < D; m++)
                s += sPr[r * D + m] * sWb[m * D + k] + sPo[r * D + m] * sWa[m * D + k];
        } else {
            for (int m = 0; m < D; m++) s += sPo[r * D + m] * sWb[m * D + k];
        }
        ((float*)g_M4)[idx] = s;
    }
}

// ---------------------------------------------------------------------------
// Project x to 16-dim: t1 = M1 x, u2 = M2 x, u3 = M3 x.
// float4 (LDS.128) inner loop; M tile XOR-swizzled: slot = row*16 + (k4^r).
// 16 nodes per 256-thread block; lane = class r; j = node-in-block.
// ---------------------------------------------------------------------------
__global__ __launch_bounds__(256) void transform_kernel(
        const float* __restrict__ x, float* __restrict__ w_out) {
    __shared__ float4 sM4[3 * NCLS * 16];  // 768 float4 = 12 KB (swizzled)
    __shared__ float4 sx4[16 * 16];        // 256 float4 = 4 KB
    const int tid = threadIdx.x;

    // Load M with XOR swizzle: element (row, k4) -> slot row*16 + (k4 ^ (row&15))
    for (int i = tid; i < 3 * NCLS * 16; i += 256) {
        const int row = i >> 4, k4 = i & 15;
        sM4[(row << 4) | (k4 ^ (row & 15))] = g_M4[i];
    }
    // Load x tile: 256 float4 = 16 nodes x 16 k4
    const int nodeBase = blockIdx.x * 16;
    sx4[tid] = ((const float4*)(x + (size_t)nodeBase * D))[tid];
    __syncthreads();

    const int j = tid >> 4;    // node within block
    const int r = tid & 15;    // class
    float a1 = 0.f, a2 = 0.f, a3 = 0.f;
    const float4* xb = &sx4[j << 4];
    #pragma unroll 4
    for (int k4 = 0; k4 < 16; k4++) {
        const float4 xv = xb[k4];
        const int sw = (r << 4) | (k4 ^ r);
        const float4 a = sM4[sw];
        const float4 b = sM4[256 + sw];
        const float4 c = sM4[512 + sw];
        a1 += a.x * xv.x + a.y * xv.y + a.z * xv.z + a.w * xv.w;
        a2 += b.x * xv.x + b.y * xv.y + b.z * xv.z + b.w * xv.w;
        a3 += c.x * xv.x + c.y * xv.y + c.z * xv.z + c.w * xv.w;
    }
    const int i = nodeBase + j;
    ((float*)g_t1)[i * NCLS + r] = a1;
    ((float*)g_u2)[i * NCLS + r] = a2;
    ((float*)g_u3)[i * NCLS + r] = a3;
    w_out[i * NCLS + r] = 0.f;
    if (r == 0) g_deg[i] = 0.f;
}

// ---------------------------------------------------------------------------
// Scatter pass 0 fused with edge packing: read raw indices (int32/int64),
// pack to g_edge for pass 1, gather t1[src], RED into out[dst], count degree.
// ---------------------------------------------------------------------------
__global__ __launch_bounds__(256) void scatter0_prep_kernel(
        float* __restrict__ dst_feat, const void* __restrict__ eidx) {
    const int e = blockIdx.x * 256 + threadIdx.x;     // grid exact: 3125*256
    int s, d;
    if (g_is64) {
        const long long* ei = (const long long*)eidx;
        s = (int)ei[e];
        d = (int)ei[NEDGES + e];
    } else {
        const int* ei = (const int*)eidx;
        s = ei[e];
        d = ei[NEDGES + e];
    }
    g_edge[e] = make_int2(s, d);
    const float4* v = &g_t1[s * (NCLS / 4)];
    float4* o = (float4*)(dst_feat + d * NCLS);
    const float4 v0 = v[0], v1 = v[1], v2 = v[2], v3 = v[3];
    atomicAdd(o + 0, v0);
    atomicAdd(o + 1, v1);
    atomicAdd(o + 2, v2);
    atomicAdd(o + 3, v3);
    atomicAdd(&g_deg[d], 1.0f);
}

// ---------------------------------------------------------------------------
// Scatter pass 1: uses packed g_edge, src = g_t2.
// ---------------------------------------------------------------------------
__global__ __launch_bounds__(256) void scatter1_kernel(float* __restrict__ dst_feat) {
    const int e = blockIdx.x * 256 + threadIdx.x;
    const int2 sd = g_edge[e];
    const float4* v = &g_t2[sd.x * (NCLS / 4)];
    float4* o = (float4*)(dst_feat + sd.y * NCLS);
    const float4 v0 = v[0], v1 = v[1], v2 = v[2], v3 = v[3];
    atomicAdd(o + 0, v0);
    atomicAdd(o + 1, v1);
    atomicAdd(o + 2, v2);
    atomicAdd(o + 3, v3);
}

// ---------------------------------------------------------------------------
// t2 = w + u2 ;  out = u3 + deg*v1 + c   (w lives in d_out, overwritten here)
// ---------------------------------------------------------------------------
__global__ __launch_bounds__(256) void combine_kernel(float* __restrict__ d_out) {
    const int q = blockIdx.x * 256 + threadIdx.x;     // < 200000 float4 slots
    const int i = q >> 2;                             // node
    const int rb = (q & 3) * 4;                       // class base
    float4 w = ((float4*)d_out)[q];
    const float4 u2 = g_u2[q];
    g_t2[q] = make_float4(w.x + u2.x, w.y + u2.y, w.z + u2.z, w.w + u2.w);
    const float dg = g_deg[i];
    const float4 u3 = g_u3[q];
    float4 r;
    r.x = u3.x + dg * g_v[rb + 0] + g_v[NCLS + rb + 0];
    r.y = u3.y + dg * g_v[rb + 1] + g_v[NCLS + rb + 1];
    r.z = u3.z + dg * g_v[rb + 2] + g_v[NCLS + rb + 2];
    r.w = u3.w + dg * g_v[rb + 3] + g_v[NCLS + rb + 3];
    ((float4*)d_out)[q] = r;
}

// ---------------------------------------------------------------------------
extern "C" void kernel_launch(void* const* d_in, const int* in_sizes, int n_in,
                              void* d_out, int out_size) {
    const float* x   = (const float*)d_in[0];
    const void*  eix = d_in[1];
    const float* W1r = (const float*)d_in[2];
    const float* b1  = (const float*)d_in[3];
    const float* W1o = (const float*)d_in[4];
    const float* W2r = (const float*)d_in[5];
    const float* b2  = (const float*)d_in[6];
    const float* W2o = (const float*)d_in[7];
    const float* Wl  = (const float*)d_in[8];
    const float* bl  = (const float*)d_in[9];
    float* out = (float*)d_out;

    // Fused dtype detect + weight fold
    dwfold_kernel<<<1, 256>>>((const unsigned int*)eix, W1r, b1, W1o, W2r, b2, W2o, Wl, bl);

    // Project to 16-dim; zero w (=d_out) and deg
    transform_kernel<<<3125, 256>>>(x, out);

    // w = A t1 (+ degree) and pack edges
    scatter0_prep_kernel<<<3125, 256>>>(out, eix);

    // t2 = w + u2 ; out = u3 + deg*v1 + c
    combine_kernel<<<782, 256>>>(out);

    // out += A t2
    scatter1_kernel<<<3125, 256>>>(out);
}